// round 16
// baseline (speedup 1.0000x reference)
#include <cuda_runtime.h>
#include <cuda_bf16.h>

#define NB     32
#define DIM    4096
#define FDIM   384
#define NGLOB  196
#define NLOC   36
#define SROWS  21760
#define TROWS  12544
#define TOTIND 30976
#define TNORM_BLKS (TROWS / 4)      // 3136
#define INIT_BLKS  242              // 242*128 = 30976 = TOTIND exactly

// ---------------- scratch (device globals; no allocations) ----------------
static __device__ float g_invt[TROWS];                    // teacher row inv-norms
static __device__ float g_tcls[64 * DIM];
static __device__ uint2 g_tprob[(size_t)TROWS * DIM / 4];
static __device__ unsigned long long g_best[TOTIND];
static __device__ double g_acc;

__constant__ int c_POFF[18] = {0,6272,7424,8576,9728,10880,12032,13184,14336,
                               15488,21760,22912,24064,25216,26368,27520,28672,29824};
__constant__ int c_SOFF[10] = {0,6272,12544,13696,14848,16000,17152,18304,19456,20608};

// ---------------- helpers ----------------
__device__ __forceinline__ float read_temp(const int* ep) {
    int e = *ep;
    if (e < 0 || e > 100000) e = (int)__int_as_float(e);
    return (e < 30) ? (0.04f + 0.03f * (float)e * (1.0f / 29.0f)) : 0.07f;
}
__device__ __forceinline__ float warpRedSum(float v) {
#pragma unroll
    for (int o = 16; o > 0; o >>= 1) v += __shfl_xor_sync(0xffffffffu, v, o);
    return v;
}
__device__ __forceinline__ float warpRedMax(float v) {
#pragma unroll
    for (int o = 16; o > 0; o >>= 1) v = fmaxf(v, __shfl_xor_sync(0xffffffffu, v, o));
    return v;
}
__device__ __forceinline__ float blkSum(float v, float* sh) {
    v = warpRedSum(v);
    if ((threadIdx.x & 31) == 0) sh[threadIdx.x >> 5] = v;
    __syncthreads();
    float r = sh[0]+sh[1]+sh[2]+sh[3]+sh[4]+sh[5]+sh[6]+sh[7];
    __syncthreads();
    return r;
}
__device__ __forceinline__ float blkMax(float v, float* sh) {
    v = warpRedMax(v);
    if ((threadIdx.x & 31) == 0) sh[threadIdx.x >> 5] = v;
    __syncthreads();
    float r = fmaxf(fmaxf(fmaxf(sh[0],sh[1]),fmaxf(sh[2],sh[3])),
                    fmaxf(fmaxf(sh[4],sh[5]),fmaxf(sh[6],sh[7])));
    __syncthreads();
    return r;
}
__device__ __forceinline__ unsigned int ordf(float f) {
    unsigned int u = __float_as_uint(f);
    return (u & 0x80000000u) ? ~u : (u | 0x80000000u);
}
__device__ __forceinline__ unsigned smem_u32(const void* p) {
    return (unsigned)__cvta_generic_to_shared(p);
}
__device__ __forceinline__ float2 bf2f(unsigned u) {
    __nv_bfloat162 h = *reinterpret_cast<__nv_bfloat162*>(&u);
    return __bfloat1622float2(h);
}
#define CP_ASYNC16(dst, src) \
    asm volatile("cp.async.ca.shared.global [%0], [%1], 16;" :: "r"(dst), "l"(src))
#define CP_COMMIT asm volatile("cp.async.commit_group;")

// ---------------- K1: teacher inv-norms (warp-per-row) + init tail ----------------
__global__ void __launch_bounds__(128) k_tnorm(const float* __restrict__ tf) {
    int bid = blockIdx.x, t = threadIdx.x;
    if (bid >= TNORM_BLKS) {
        int i = (bid - TNORM_BLKS) * 128 + t;   // exactly covers TOTIND
        if (i == 0) g_acc = 0.0;
        g_best[i] = 0ull;
        return;
    }
    int w = t >> 5, lane = t & 31;
    int row = bid * 4 + w;
    const float4* src = (const float4*)(tf + (size_t)row * FDIM);
    float4 a = src[lane], b = src[lane + 32], c = src[lane + 64];
    float ss = a.x*a.x + a.y*a.y + a.z*a.z + a.w*a.w
             + b.x*b.x + b.y*b.y + b.z*b.z + b.w*b.w
             + c.x*c.x + c.y*c.y + c.z*c.z + c.w*c.w;
    ss = warpRedSum(ss);
    if (lane == 0) g_invt[row] = 1.0f / fmaxf(sqrtf(ss), 1e-12f);
}

// ---------------- K2: teacher cls softmax (64 rows) ----------------
__global__ void __launch_bounds__(256) k_tcls(const float* __restrict__ tcls,
                                              const float* __restrict__ center,
                                              const int* __restrict__ ep) {
    __shared__ float sh[8];
    int row = blockIdx.x, tid = threadIdx.x;
    float it = 1.0f / read_temp(ep);
    const float4* xp = (const float4*)(tcls + (size_t)row * DIM);
    const float4* cp = (const float4*)center;
    float y[16];
#pragma unroll
    for (int k = 0; k < 4; k++) {
        float4 x = xp[tid + 256 * k], c = cp[tid + 256 * k];
        y[4*k+0] = (x.x - c.x) * it; y[4*k+1] = (x.y - c.y) * it;
        y[4*k+2] = (x.z - c.z) * it; y[4*k+3] = (x.w - c.w) * it;
    }
    float mx = -3.4e38f;
#pragma unroll
    for (int k = 0; k < 16; k++) mx = fmaxf(mx, y[k]);
    mx = blkMax(mx, sh);
    float se = 0.f;
#pragma unroll
    for (int k = 0; k < 16; k++) { y[k] = __expf(y[k] - mx); se += y[k]; }
    se = blkSum(se, sh);
    float inv = 1.0f / se;
    float4* op = (float4*)(g_tcls + (size_t)row * DIM);
#pragma unroll
    for (int k = 0; k < 4; k++)
        op[tid + 256 * k] = make_float4(y[4*k+0]*inv, y[4*k+1]*inv, y[4*k+2]*inv, y[4*k+3]*inv);
}

// ---------------- K3: teacher region softmax -> bf16 probs ----------------
__global__ void __launch_bounds__(256) k_prob(const float* __restrict__ treg,
                                              const float* __restrict__ cgrid,
                                              const int* __restrict__ ep) {
    __shared__ float sh[8];
    int row = blockIdx.x, tid = threadIdx.x;
    float it = 1.0f / read_temp(ep);
    const float4* xp = (const float4*)(treg + (size_t)row * DIM);
    const float4* cp = (const float4*)cgrid;
    float y[16];
#pragma unroll
    for (int k = 0; k < 4; k++) {
        float4 x = __ldcs(xp + tid + 256 * k);
        float4 c = cp[tid + 256 * k];
        y[4*k+0] = (x.x - c.x) * it; y[4*k+1] = (x.y - c.y) * it;
        y[4*k+2] = (x.z - c.z) * it; y[4*k+3] = (x.w - c.w) * it;
    }
    float mx = -3.4e38f;
#pragma unroll
    for (int k = 0; k < 16; k++) mx = fmaxf(mx, y[k]);
    mx = blkMax(mx, sh);
    float se = 0.f;
#pragma unroll
    for (int k = 0; k < 16; k++) { y[k] = __expf(y[k] - mx); se += y[k]; }
    se = blkSum(se, sh);
    float inv = 1.0f / se;
    uint2* op = g_tprob + (size_t)row * (DIM / 4);
#pragma unroll
    for (int k = 0; k < 4; k++) {
        __nv_bfloat162 h0 = __float22bfloat162_rn(make_float2(y[4*k+0]*inv, y[4*k+1]*inv));
        __nv_bfloat162 h1 = __float22bfloat162_rn(make_float2(y[4*k+2]*inv, y[4*k+3]*inv));
        uint2 u;
        u.x = *reinterpret_cast<unsigned int*>(&h0);
        u.y = *reinterpret_cast<unsigned int*>(&h1);
        op[tid + 256 * k] = u;
    }
}

// ---------------- K4: sim argmax on RAW feats, teacher-norm in epilogue ----------------
__device__ __forceinline__ int srow_of(int i, int b, int r) {
    if (r >= 484) r = 483;
    if (r < 196) {
        int j = (i == 0) ? 1 : 0;
        return c_SOFF[j] + b * NGLOB + r;
    }
    int lr = r - 196;
    int lj = lr / 36;
    int s = lr - lj * 36;
    return c_SOFF[lj + 2] + b * NLOC + s;
}

__global__ void __launch_bounds__(256, 4) k_sim(const float* __restrict__ sf,
                                                const float* __restrict__ tf) {
    __shared__ __align__(16) float As[2][64][20];
    __shared__ __align__(16) float Bs[2][208][20];

    int t = threadIdx.x;
    int mt = blockIdx.x & 7;
    int b  = (blockIdx.x >> 3) & 31;
    int i  = blockIdx.x >> 8;
    int trow0 = i * 6272 + b * NGLOB;

    int lane = t & 31, wid = t >> 5;
    int warpM = wid >> 1, warpN = wid & 1;
    int g = lane >> 2, tig = lane & 3;
    int mb = warpM * 16, nb = warpN * 104;

    int arow = t >> 2, akq = t & 3;
    const float* a_src = sf + (size_t)srow_of(i, b, mt * 64 + arow) * FDIM + akq * 4;
    unsigned sA = smem_u32(&As[0][0][0]);
    unsigned sB = smem_u32(&Bs[0][0][0]);
    unsigned dA = sA + arow * 80 + akq * 16;

    const float* b_src[4]; unsigned dB[4];
#pragma unroll
    for (int it = 0; it < 4; it++) {
        int u = t + it * 256;
        int uu = (u < 832) ? u : 831;
        int n = uu >> 2, kq = uu & 3;
        int gn = (n > 195) ? 195 : n;
        b_src[it] = tf + (size_t)(trow0 + gn) * FDIM + kq * 4;
        dB[it] = sB + n * 80 + kq * 16;
    }
    bool b3 = (t < 64);

    float acc[13][4];
#pragma unroll
    for (int q = 0; q < 13; q++) {
        acc[q][0] = 0.f; acc[q][1] = 0.f; acc[q][2] = 0.f; acc[q][3] = 0.f;
    }

    {
        CP_ASYNC16(dA, a_src);
        CP_ASYNC16(dB[0], b_src[0]);
        CP_ASYNC16(dB[1], b_src[1]);
        CP_ASYNC16(dB[2], b_src[2]);
        if (b3) CP_ASYNC16(dB[3], b_src[3]);
        CP_COMMIT;
    }

    for (int ch = 0; ch < 24; ch++) {
        int buf = ch & 1;
        if (ch + 1 < 24) {
            int nb2 = (buf ^ 1) ? 1 : 0;
            unsigned aoff = nb2 * 5120u, boff = nb2 * 16640u;
            const float* ap = a_src + (ch + 1) * 16;
            CP_ASYNC16(dA + aoff, ap);
            CP_ASYNC16(dB[0] + boff, b_src[0] + (ch + 1) * 16);
            CP_ASYNC16(dB[1] + boff, b_src[1] + (ch + 1) * 16);
            CP_ASYNC16(dB[2] + boff, b_src[2] + (ch + 1) * 16);
            if (b3) CP_ASYNC16(dB[3] + boff, b_src[3] + (ch + 1) * 16);
            CP_COMMIT;
            asm volatile("cp.async.wait_group 1;");
        } else {
            asm volatile("cp.async.wait_group 0;");
        }
        __syncthreads();
#pragma unroll
        for (int ks = 0; ks < 2; ks++) {
            int kof = ks * 8;
            unsigned a0 = __float_as_uint(As[buf][mb + g    ][kof + tig    ]);
            unsigned a1 = __float_as_uint(As[buf][mb + g + 8][kof + tig    ]);
            unsigned a2 = __float_as_uint(As[buf][mb + g    ][kof + tig + 4]);
            unsigned a3 = __float_as_uint(As[buf][mb + g + 8][kof + tig + 4]);
#pragma unroll
            for (int q = 0; q < 13; q++) {
                unsigned b0 = __float_as_uint(Bs[buf][nb + q * 8 + g][kof + tig    ]);
                unsigned b1 = __float_as_uint(Bs[buf][nb + q * 8 + g][kof + tig + 4]);
                asm volatile(
                    "mma.sync.aligned.m16n8k8.row.col.f32.tf32.tf32.f32 "
                    "{%0,%1,%2,%3}, {%4,%5,%6,%7}, {%8,%9}, {%0,%1,%2,%3};\n"
                    : "+f"(acc[q][0]), "+f"(acc[q][1]), "+f"(acc[q][2]), "+f"(acc[q][3])
                    : "r"(a0), "r"(a1), "r"(a2), "r"(a3), "r"(b0), "r"(b1));
            }
        }
        __syncthreads();
    }

    // stage teacher inv-norms for this (i,b) into (now-free) smem
    float* invsh = &As[0][0][0];
    if (t < NGLOB) invsh[t] = g_invt[trow0 + t];
    __syncthreads();

    unsigned long long key0 = 0ull, key1 = 0ull;
#pragma unroll
    for (int q = 0; q < 13; q++) {
        int n0 = nb + q * 8 + 2 * tig;
#pragma unroll
        for (int d = 0; d < 2; d++) {
            int n = n0 + d;
            if (n < NGLOB) {
                float inv = invsh[n];
                unsigned long long kk0 =
                    ((unsigned long long)ordf(acc[q][d] * inv) << 32) | (unsigned)(0xFFFF - n);
                if (kk0 > key0) key0 = kk0;
                unsigned long long kk1 =
                    ((unsigned long long)ordf(acc[q][2 + d] * inv) << 32) | (unsigned)(0xFFFF - n);
                if (kk1 > key1) key1 = kk1;
            }
        }
    }
#pragma unroll
    for (int m = 1; m < 4; m <<= 1) {
        unsigned long long o0 = __shfl_xor_sync(0xffffffffu, key0, m);
        if (o0 > key0) key0 = o0;
        unsigned long long o1 = __shfl_xor_sync(0xffffffffu, key1, m);
        if (o1 > key1) key1 = o1;
    }
    if (tig == 0) {
#pragma unroll
        for (int d = 0; d < 2; d++) {
            int r = mt * 64 + mb + g + d * 8;
            unsigned long long key = d ? key1 : key0;
            if (r < 484) {
                int p, s, S;
                if (r < 196) { p = (i == 0) ? 0 : 9; s = r; S = NGLOB; }
                else {
                    int lr = r - 196;
                    int lj = lr / 36;
                    s = lr - lj * 36; S = NLOC;
                    p = (i == 0) ? (lj + 1) : (lj + 10);
                }
                atomicMax(&g_best[c_POFF[p] + b * S + s], key);
            }
        }
    }
}

// ---------------- K5: region + cls merged; cls q folded at load ----------------
__global__ void __launch_bounds__(256) k_regcls(const float* __restrict__ sreg,
                                                const float* __restrict__ scls) {
    __shared__ float sh[8];
    int tid = threadIdx.x;

    if (blockIdx.x >= SROWS) {
        int idx = blockIdx.x - SROWS;
        int p = idx >> 5, b = idx & 31;
        int i = (p < 9) ? 0 : 1;
        int j = (p < 9) ? ((p == 0) ? 1 : p + 1) : ((p == 9) ? 0 : p - 8);
        const float4* vp = (const float4*)(scls + (size_t)(j * NB + b) * DIM);
        const float4* qp = (const float4*)(g_tcls + (size_t)(i * NB + b) * DIM);
        float v[16];
        float qv = 0.f;
#pragma unroll
        for (int k = 0; k < 4; k++) {
            float4 a = vp[tid + 256 * k], c = qp[tid + 256 * k];
            v[4*k+0] = a.x * 10.f; v[4*k+1] = a.y * 10.f; v[4*k+2] = a.z * 10.f; v[4*k+3] = a.w * 10.f;
            qv += c.x * v[4*k+0]; qv += c.y * v[4*k+1];
            qv += c.z * v[4*k+2]; qv += c.w * v[4*k+3];
        }
        float mx = -3.4e38f;
#pragma unroll
        for (int k = 0; k < 16; k++) mx = fmaxf(mx, v[k]);
        mx = blkMax(mx, sh);
        float se = 0.f;
#pragma unroll
        for (int k = 0; k < 16; k++) se += __expf(v[k] - mx);
        se = blkSum(se, sh);
        qv = blkSum(qv, sh);
        if (tid == 0) {
            float lse = mx + logf(se);
            atomicAdd(&g_acc, (double)(lse - qv) * (0.5 / (32.0 * 18.0)));
        }
        return;
    }

    int row = blockIdx.x;
    int j, b, s;
    if (row < 12544) { j = row / 6272; int r = row - j * 6272; b = r / NGLOB; s = r - b * NGLOB; }
    else { int lr = row - 12544; j = 2 + lr / 1152; int r = lr % 1152; b = r / NLOC; s = r - b * NLOC; }
    int S = (j < 2) ? NGLOB : NLOC;

    int np, iA, pA, iB = 1, pB = 0;
    if (j == 0)      { np = 1; iA = 1; pA = 9; }
    else if (j == 1) { np = 1; iA = 0; pA = 0; }
    else             { np = 2; iA = 0; pA = j - 1; iB = 1; pB = j + 8; }

    unsigned long long keyA = g_best[c_POFF[pA] + b * S + s];
    unsigned long long keyB = (np == 2) ? g_best[c_POFF[pB] + b * S + s] : 0ull;

    const float4* sp = (const float4*)(sreg + (size_t)row * DIM);
    float4 v[4];
#pragma unroll
    for (int k = 0; k < 4; k++) {
        float4 t = __ldcs(sp + tid + 256 * k);
        v[k] = make_float4(t.x * 10.f, t.y * 10.f, t.z * 10.f, t.w * 10.f);
    }

    int nA = 0xFFFF - (int)(keyA & 0xFFFFull);
    int trA = iA * 6272 + b * NGLOB + nA;
    const uint2* ppA = g_tprob + (size_t)trA * (DIM / 4);
    uint2 prA[4];
#pragma unroll
    for (int k = 0; k < 4; k++) prA[k] = ppA[tid + 256 * k];
    uint2 prB[4];
    if (np == 2) {
        int nB2 = 0xFFFF - (int)(keyB & 0xFFFFull);
        int trB = iB * 6272 + b * NGLOB + nB2;
        const uint2* ppB = g_tprob + (size_t)trB * (DIM / 4);
#pragma unroll
        for (int k = 0; k < 4; k++) prB[k] = ppB[tid + 256 * k];
    }

    float mx = -3.4e38f;
#pragma unroll
    for (int k = 0; k < 4; k++)
        mx = fmaxf(mx, fmaxf(fmaxf(v[k].x, v[k].y), fmaxf(v[k].z, v[k].w)));
    mx = blkMax(mx, sh);
    float se = 0.f;
#pragma unroll
    for (int k = 0; k < 4; k++)
        se += __expf(v[k].x - mx) + __expf(v[k].y - mx) + __expf(v[k].z - mx) + __expf(v[k].w - mx);
    se = blkSum(se, sh);
    float lse = mx + logf(se);

    float partA = 0.f, partB = 0.f;
#pragma unroll
    for (int k = 0; k < 4; k++) {
        float2 f0 = bf2f(prA[k].x);
        float2 f1 = bf2f(prA[k].y);
        partA += f0.x * v[k].x + f0.y * v[k].y + f1.x * v[k].z + f1.y * v[k].w;
    }
    if (np == 2) {
#pragma unroll
        for (int k = 0; k < 4; k++) {
            float2 f0 = bf2f(prB[k].x);
            float2 f1 = bf2f(prB[k].y);
            partB += f0.x * v[k].x + f0.y * v[k].y + f1.x * v[k].z + f1.y * v[k].w;
        }
    }
    float dotsum = blkSum(partA + partB, sh);

    if (tid == 0) {
        double contrib = ((double)np * (double)lse - (double)dotsum)
                       * (0.5 / ((double)S * 32.0 * 18.0));
        atomicAdd(&g_acc, contrib);
    }
}

// ---------------- K6: finalize ----------------
__global__ void k_fin(float* out) { out[0] = (float)g_acc; }

// ---------------- launch ----------------
extern "C" void kernel_launch(void* const* d_in, const int* in_sizes, int n_in,
                              void* d_out, int out_size) {
    (void)in_sizes; (void)n_in; (void)out_size;
    const float* s_cls  = (const float*)d_in[0];
    const float* s_reg  = (const float*)d_in[1];
    const float* s_fea  = (const float*)d_in[2];
    const float* t_cls  = (const float*)d_in[3];
    const float* t_reg  = (const float*)d_in[4];
    const float* t_fea  = (const float*)d_in[5];
    const float* center = (const float*)d_in[6];
    const float* cgrid  = (const float*)d_in[7];
    const int*   ep     = (const int*)d_in[8];

    static cudaStream_t s2 = nullptr;
    static cudaEvent_t e_fork = nullptr, e_join = nullptr;
    if (!s2) {
        cudaStreamCreateWithFlags(&s2, cudaStreamNonBlocking);
        cudaEventCreateWithFlags(&e_fork, cudaEventDisableTiming);
        cudaEventCreateWithFlags(&e_join, cudaEventDisableTiming);
    }

    // fork: prob + tcls on distinct stream
    cudaEventRecord(e_fork, cudaStreamPerThread);
    cudaStreamWaitEvent(s2, e_fork, 0);
    k_prob<<<TROWS, 256, 0, s2>>>(t_reg, cgrid, ep);
    k_tcls<<<64, 256, 0, s2>>>(t_cls, center, ep);
    cudaEventRecord(e_join, s2);

    // main chain: tnorm (+init tail), sim on raw feats
    k_tnorm<<<TNORM_BLKS + INIT_BLKS, 128>>>(t_fea);
    k_sim<<<512, 256>>>(s_fea, t_fea);

    // join, then region+cls and finalize
    cudaStreamWaitEvent(cudaStreamPerThread, e_join, 0);
    k_regcls<<<SROWS + 576, 256>>>(s_reg, s_cls);
    k_fin<<<1, 1>>>((float*)d_out);
}

// round 17
// speedup vs baseline: 1.5266x; 1.5266x over previous
#include <cuda_runtime.h>
#include <cuda_bf16.h>

#define NB     32
#define DIM    4096
#define FDIM   384
#define NGLOB  196
#define NLOC   36
#define SROWS  21760
#define TROWS  12544
#define TOTIND 30976
#define TN_BLKS 3136     // teacher: 4 rows/block
#define SC_BLKS 5440     // student convert: 4 rows/block
#define INIT_BLKS 242    // 242*128 = 30976 exactly

// ---------------- scratch (device globals; no allocations) ----------------
static __device__ float g_invt[TROWS];
static __device__ __nv_bfloat16 g_sfeb[(size_t)SROWS * FDIM];
static __device__ __nv_bfloat16 g_tfeb[(size_t)TROWS * FDIM];
static __device__ float g_tcls[64 * DIM];
static __device__ uint2 g_tprob[(size_t)TROWS * DIM / 4];
static __device__ unsigned long long g_best[TOTIND];
static __device__ double g_acc;

__constant__ int c_POFF[18] = {0,6272,7424,8576,9728,10880,12032,13184,14336,
                               15488,21760,22912,24064,25216,26368,27520,28672,29824};
__constant__ int c_SOFF[10] = {0,6272,12544,13696,14848,16000,17152,18304,19456,20608};

// ---------------- helpers ----------------
__device__ __forceinline__ float read_temp(const int* ep) {
    int e = *ep;
    if (e < 0 || e > 100000) e = (int)__int_as_float(e);
    return (e < 30) ? (0.04f + 0.03f * (float)e * (1.0f / 29.0f)) : 0.07f;
}
__device__ __forceinline__ float warpRedSum(float v) {
#pragma unroll
    for (int o = 16; o > 0; o >>= 1) v += __shfl_xor_sync(0xffffffffu, v, o);
    return v;
}
__device__ __forceinline__ float warpRedMax(float v) {
#pragma unroll
    for (int o = 16; o > 0; o >>= 1) v = fmaxf(v, __shfl_xor_sync(0xffffffffu, v, o));
    return v;
}
__device__ __forceinline__ float blkSum(float v, float* sh) {
    v = warpRedSum(v);
    if ((threadIdx.x & 31) == 0) sh[threadIdx.x >> 5] = v;
    __syncthreads();
    float r = sh[0]+sh[1]+sh[2]+sh[3]+sh[4]+sh[5]+sh[6]+sh[7];
    __syncthreads();
    return r;
}
__device__ __forceinline__ float blkMax(float v, float* sh) {
    v = warpRedMax(v);
    if ((threadIdx.x & 31) == 0) sh[threadIdx.x >> 5] = v;
    __syncthreads();
    float r = fmaxf(fmaxf(fmaxf(sh[0],sh[1]),fmaxf(sh[2],sh[3])),
                    fmaxf(fmaxf(sh[4],sh[5]),fmaxf(sh[6],sh[7])));
    __syncthreads();
    return r;
}
__device__ __forceinline__ unsigned int ordf(float f) {
    unsigned int u = __float_as_uint(f);
    return (u & 0x80000000u) ? ~u : (u | 0x80000000u);
}
__device__ __forceinline__ unsigned smem_u32(const void* p) {
    return (unsigned)__cvta_generic_to_shared(p);
}
__device__ __forceinline__ float2 bf2f(unsigned u) {
    __nv_bfloat162 h = *reinterpret_cast<__nv_bfloat162*>(&u);
    return __bfloat1622float2(h);
}
__device__ __forceinline__ uint2 f4_to_bf(float4 v) {
    __nv_bfloat162 lo = __float22bfloat162_rn(make_float2(v.x, v.y));
    __nv_bfloat162 hi = __float22bfloat162_rn(make_float2(v.z, v.w));
    uint2 u;
    u.x = *reinterpret_cast<unsigned*>(&lo);
    u.y = *reinterpret_cast<unsigned*>(&hi);
    return u;
}
#define CP_ASYNC16(dst, src) \
    asm volatile("cp.async.ca.shared.global [%0], [%1], 16;" :: "r"(dst), "l"(src))
#define CP_COMMIT asm volatile("cp.async.commit_group;")

// ---------------- K1: prep = teacher inv-norms + bf16 converts + init ----------------
__global__ void __launch_bounds__(128) k_prep(const float* __restrict__ sf,
                                              const float* __restrict__ tf) {
    int bid = blockIdx.x, t = threadIdx.x;
    int w = t >> 5, lane = t & 31;

    if (bid < TN_BLKS) {
        // teacher: norm + bf16 convert
        int row = bid * 4 + w;
        const float4* src = (const float4*)(tf + (size_t)row * FDIM);
        float4 a = src[lane], b = src[lane + 32], c = src[lane + 64];
        float ss = a.x*a.x + a.y*a.y + a.z*a.z + a.w*a.w
                 + b.x*b.x + b.y*b.y + b.z*b.z + b.w*b.w
                 + c.x*c.x + c.y*c.y + c.z*c.z + c.w*c.w;
        ss = warpRedSum(ss);
        if (lane == 0) g_invt[row] = 1.0f / fmaxf(sqrtf(ss), 1e-12f);
        uint2* dst = (uint2*)(g_tfeb + (size_t)row * FDIM);
        dst[lane] = f4_to_bf(a); dst[lane + 32] = f4_to_bf(b); dst[lane + 64] = f4_to_bf(c);
        return;
    }
    bid -= TN_BLKS;
    if (bid < SC_BLKS) {
        // student: bf16 convert only
        int row = bid * 4 + w;
        const float4* src = (const float4*)(sf + (size_t)row * FDIM);
        float4 a = __ldcs(src + lane), b = __ldcs(src + lane + 32), c = __ldcs(src + lane + 64);
        uint2* dst = (uint2*)(g_sfeb + (size_t)row * FDIM);
        dst[lane] = f4_to_bf(a); dst[lane + 32] = f4_to_bf(b); dst[lane + 64] = f4_to_bf(c);
        return;
    }
    bid -= SC_BLKS;
    int i = bid * 128 + t;   // exactly covers TOTIND
    if (i == 0) g_acc = 0.0;
    g_best[i] = 0ull;
}

// ---------------- K2: teacher cls softmax (64 rows) ----------------
__global__ void __launch_bounds__(256) k_tcls(const float* __restrict__ tcls,
                                              const float* __restrict__ center,
                                              const int* __restrict__ ep) {
    __shared__ float sh[8];
    int row = blockIdx.x, tid = threadIdx.x;
    float it = 1.0f / read_temp(ep);
    const float4* xp = (const float4*)(tcls + (size_t)row * DIM);
    const float4* cp = (const float4*)center;
    float y[16];
#pragma unroll
    for (int k = 0; k < 4; k++) {
        float4 x = xp[tid + 256 * k], c = cp[tid + 256 * k];
        y[4*k+0] = (x.x - c.x) * it; y[4*k+1] = (x.y - c.y) * it;
        y[4*k+2] = (x.z - c.z) * it; y[4*k+3] = (x.w - c.w) * it;
    }
    float mx = -3.4e38f;
#pragma unroll
    for (int k = 0; k < 16; k++) mx = fmaxf(mx, y[k]);
    mx = blkMax(mx, sh);
    float se = 0.f;
#pragma unroll
    for (int k = 0; k < 16; k++) { y[k] = __expf(y[k] - mx); se += y[k]; }
    se = blkSum(se, sh);
    float inv = 1.0f / se;
    float4* op = (float4*)(g_tcls + (size_t)row * DIM);
#pragma unroll
    for (int k = 0; k < 4; k++)
        op[tid + 256 * k] = make_float4(y[4*k+0]*inv, y[4*k+1]*inv, y[4*k+2]*inv, y[4*k+3]*inv);
}

// ---------------- K3: teacher region softmax -> bf16 probs ----------------
__global__ void __launch_bounds__(256) k_prob(const float* __restrict__ treg,
                                              const float* __restrict__ cgrid,
                                              const int* __restrict__ ep) {
    __shared__ float sh[8];
    int row = blockIdx.x, tid = threadIdx.x;
    float it = 1.0f / read_temp(ep);
    const float4* xp = (const float4*)(treg + (size_t)row * DIM);
    const float4* cp = (const float4*)cgrid;
    float y[16];
#pragma unroll
    for (int k = 0; k < 4; k++) {
        float4 x = __ldcs(xp + tid + 256 * k);
        float4 c = cp[tid + 256 * k];
        y[4*k+0] = (x.x - c.x) * it; y[4*k+1] = (x.y - c.y) * it;
        y[4*k+2] = (x.z - c.z) * it; y[4*k+3] = (x.w - c.w) * it;
    }
    float mx = -3.4e38f;
#pragma unroll
    for (int k = 0; k < 16; k++) mx = fmaxf(mx, y[k]);
    mx = blkMax(mx, sh);
    float se = 0.f;
#pragma unroll
    for (int k = 0; k < 16; k++) { y[k] = __expf(y[k] - mx); se += y[k]; }
    se = blkSum(se, sh);
    float inv = 1.0f / se;
    uint2* op = g_tprob + (size_t)row * (DIM / 4);
#pragma unroll
    for (int k = 0; k < 4; k++) {
        __nv_bfloat162 h0 = __float22bfloat162_rn(make_float2(y[4*k+0]*inv, y[4*k+1]*inv));
        __nv_bfloat162 h1 = __float22bfloat162_rn(make_float2(y[4*k+2]*inv, y[4*k+3]*inv));
        uint2 u;
        u.x = *reinterpret_cast<unsigned int*>(&h0);
        u.y = *reinterpret_cast<unsigned int*>(&h1);
        op[tid + 256 * k] = u;
    }
}

// ---------------- K4: sim argmax, bf16 m16n8k16, teacher-norm in epilogue ----------------
__device__ __forceinline__ int srow_of(int i, int b, int r) {
    if (r >= 484) r = 483;
    if (r < 196) {
        int j = (i == 0) ? 1 : 0;
        return c_SOFF[j] + b * NGLOB + r;
    }
    int lr = r - 196;
    int lj = lr / 36;
    int s = lr - lj * 36;
    return c_SOFF[lj + 2] + b * NLOC + s;
}

// smem rows padded to 24 bf16 (48B): bank = (12*row + tig) pattern -> conflict-free
__global__ void __launch_bounds__(256) k_sim() {
    __shared__ __align__(16) __nv_bfloat16 As[2][64][24];
    __shared__ __align__(16) __nv_bfloat16 Bs[2][208][24];

    int t = threadIdx.x;
    int mt = blockIdx.x & 7;
    int b  = (blockIdx.x >> 3) & 31;
    int i  = blockIdx.x >> 8;
    int trow0 = i * 6272 + b * NGLOB;

    int lane = t & 31, wid = t >> 5;
    int warpM = wid >> 1, warpN = wid & 1;
    int g = lane >> 2, tig = lane & 3;
    int mb = warpM * 16, nb = warpN * 104;

    unsigned sA = smem_u32(&As[0][0][0]);
    unsigned sB = smem_u32(&Bs[0][0][0]);

    // A tasks: 128 (64 rows x 2 segs), threads t<128
    bool doA = (t < 128);
    int arow = (t >> 1) & 63, aseg = t & 1;
    const __nv_bfloat16* a_src =
        g_sfeb + (size_t)srow_of(i, b, mt * 64 + arow) * FDIM + aseg * 8;
    unsigned dA = sA + arow * 48 + aseg * 16;

    // B tasks: 416 (208 rows x 2 segs): t and (t+256 if t<160)
    int n0_ = t >> 1, seg0 = t & 1;
    int gn0 = (n0_ > 195) ? 195 : n0_;
    const __nv_bfloat16* b_src0 = g_tfeb + (size_t)(trow0 + gn0) * FDIM + seg0 * 8;
    unsigned dB0 = sB + n0_ * 48 + seg0 * 16;
    bool doB1 = (t < 160);
    int u1 = t + 256;
    int n1_ = u1 >> 1, seg1 = u1 & 1;
    int gn1 = (n1_ > 195) ? 195 : n1_;
    const __nv_bfloat16* b_src1 = g_tfeb + (size_t)(trow0 + gn1) * FDIM + seg1 * 8;
    unsigned dB1 = sB + n1_ * 48 + seg1 * 16;

    float acc[13][4];
#pragma unroll
    for (int q = 0; q < 13; q++) {
        acc[q][0] = 0.f; acc[q][1] = 0.f; acc[q][2] = 0.f; acc[q][3] = 0.f;
    }

    // prefetch chunk 0 into buf 0 (chunk = 16 k-elems = 32B/row)
    {
        if (doA) CP_ASYNC16(dA, a_src);
        CP_ASYNC16(dB0, b_src0);
        if (doB1) CP_ASYNC16(dB1, b_src1);
        CP_COMMIT;
    }

    for (int ch = 0; ch < 24; ch++) {
        int buf = ch & 1;
        if (ch + 1 < 24) {
            int nb2 = buf ^ 1;
            unsigned aoff = nb2 * 3072u, boff = nb2 * 9984u;
            if (doA) CP_ASYNC16(dA + aoff, a_src + (ch + 1) * 16);
            CP_ASYNC16(dB0 + boff, b_src0 + (ch + 1) * 16);
            if (doB1) CP_ASYNC16(dB1 + boff, b_src1 + (ch + 1) * 16);
            CP_COMMIT;
            asm volatile("cp.async.wait_group 1;");
        } else {
            asm volatile("cp.async.wait_group 0;");
        }
        __syncthreads();
        {
            unsigned a0 = *(const unsigned*)&As[buf][mb + g    ][2 * tig    ];
            unsigned a1 = *(const unsigned*)&As[buf][mb + g + 8][2 * tig    ];
            unsigned a2 = *(const unsigned*)&As[buf][mb + g    ][2 * tig + 8];
            unsigned a3 = *(const unsigned*)&As[buf][mb + g + 8][2 * tig + 8];
#pragma unroll
            for (int q = 0; q < 13; q++) {
                unsigned b0 = *(const unsigned*)&Bs[buf][nb + q * 8 + g][2 * tig    ];
                unsigned b1 = *(const unsigned*)&Bs[buf][nb + q * 8 + g][2 * tig + 8];
                asm volatile(
                    "mma.sync.aligned.m16n8k16.row.col.f32.bf16.bf16.f32 "
                    "{%0,%1,%2,%3}, {%4,%5,%6,%7}, {%8,%9}, {%0,%1,%2,%3};\n"
                    : "+f"(acc[q][0]), "+f"(acc[q][1]), "+f"(acc[q][2]), "+f"(acc[q][3])
                    : "r"(a0), "r"(a1), "r"(a2), "r"(a3), "r"(b0), "r"(b1));
            }
        }
        __syncthreads();
    }

    // stage teacher inv-norms into (now-free) smem
    float* invsh = (float*)&As[0][0][0];
    if (t < NGLOB) invsh[t] = g_invt[trow0 + t];
    __syncthreads();

    unsigned long long key0 = 0ull, key1 = 0ull;
#pragma unroll
    for (int q = 0; q < 13; q++) {
        int n0 = nb + q * 8 + 2 * tig;
#pragma unroll
        for (int d = 0; d < 2; d++) {
            int n = n0 + d;
            if (n < NGLOB) {
                float inv = invsh[n];
                unsigned long long kk0 =
                    ((unsigned long long)ordf(acc[q][d] * inv) << 32) | (unsigned)(0xFFFF - n);
                if (kk0 > key0) key0 = kk0;
                unsigned long long kk1 =
                    ((unsigned long long)ordf(acc[q][2 + d] * inv) << 32) | (unsigned)(0xFFFF - n);
                if (kk1 > key1) key1 = kk1;
            }
        }
    }
#pragma unroll
    for (int m = 1; m < 4; m <<= 1) {
        unsigned long long o0 = __shfl_xor_sync(0xffffffffu, key0, m);
        if (o0 > key0) key0 = o0;
        unsigned long long o1 = __shfl_xor_sync(0xffffffffu, key1, m);
        if (o1 > key1) key1 = o1;
    }
    if (tig == 0) {
#pragma unroll
        for (int d = 0; d < 2; d++) {
            int r = mt * 64 + mb + g + d * 8;
            unsigned long long key = d ? key1 : key0;
            if (r < 484) {
                int p, s, S;
                if (r < 196) { p = (i == 0) ? 0 : 9; s = r; S = NGLOB; }
                else {
                    int lr = r - 196;
                    int lj = lr / 36;
                    s = lr - lj * 36; S = NLOC;
                    p = (i == 0) ? (lj + 1) : (lj + 10);
                }
                atomicMax(&g_best[c_POFF[p] + b * S + s], key);
            }
        }
    }
}

// ---------------- K5: region + cls merged (R15 champion version) ----------------
__global__ void __launch_bounds__(256) k_regcls(const float* __restrict__ sreg,
                                                const float* __restrict__ scls) {
    __shared__ float sh[8];
    int tid = threadIdx.x;

    if (blockIdx.x >= SROWS) {
        int idx = blockIdx.x - SROWS;
        int p = idx >> 5, b = idx & 31;
        int i = (p < 9) ? 0 : 1;
        int j = (p < 9) ? ((p == 0) ? 1 : p + 1) : ((p == 9) ? 0 : p - 8);
        const float4* vp = (const float4*)(scls + (size_t)(j * NB + b) * DIM);
        const float4* qp = (const float4*)(g_tcls + (size_t)(i * NB + b) * DIM);
        float v[16];
        float qv = 0.f;
#pragma unroll
        for (int k = 0; k < 4; k++) {
            float4 a = vp[tid + 256 * k], c = qp[tid + 256 * k];
            v[4*k+0] = a.x * 10.f; v[4*k+1] = a.y * 10.f; v[4*k+2] = a.z * 10.f; v[4*k+3] = a.w * 10.f;
            qv += c.x * v[4*k+0]; qv += c.y * v[4*k+1];
            qv += c.z * v[4*k+2]; qv += c.w * v[4*k+3];
        }
        float mx = -3.4e38f;
#pragma unroll
        for (int k = 0; k < 16; k++) mx = fmaxf(mx, v[k]);
        mx = blkMax(mx, sh);
        float se = 0.f;
#pragma unroll
        for (int k = 0; k < 16; k++) se += __expf(v[k] - mx);
        se = blkSum(se, sh);
        qv = blkSum(qv, sh);
        if (tid == 0) {
            float lse = mx + logf(se);
            atomicAdd(&g_acc, (double)(lse - qv) * (0.5 / (32.0 * 18.0)));
        }
        return;
    }

    int row = blockIdx.x;
    int j, b, s;
    if (row < 12544) { j = row / 6272; int r = row - j * 6272; b = r / NGLOB; s = r - b * NGLOB; }
    else { int lr = row - 12544; j = 2 + lr / 1152; int r = lr % 1152; b = r / NLOC; s = r - b * NLOC; }
    int S = (j < 2) ? NGLOB : NLOC;

    int np, iA, pA, iB = 1, pB = 0;
    if (j == 0)      { np = 1; iA = 1; pA = 9; }
    else if (j == 1) { np = 1; iA = 0; pA = 0; }
    else             { np = 2; iA = 0; pA = j - 1; iB = 1; pB = j + 8; }

    unsigned long long keyA = g_best[c_POFF[pA] + b * S + s];
    unsigned long long keyB = (np == 2) ? g_best[c_POFF[pB] + b * S + s] : 0ull;

    const float4* sp = (const float4*)(sreg + (size_t)row * DIM);
    float4 v[4];
#pragma unroll
    for (int k = 0; k < 4; k++) {
        float4 t = __ldcs(sp + tid + 256 * k);
        v[k] = make_float4(t.x * 10.f, t.y * 10.f, t.z * 10.f, t.w * 10.f);
    }

    int nA = 0xFFFF - (int)(keyA & 0xFFFFull);
    int trA = iA * 6272 + b * NGLOB + nA;
    const uint2* ppA = g_tprob + (size_t)trA * (DIM / 4);
    uint2 prA[4];
#pragma unroll
    for (int k = 0; k < 4; k++) prA[k] = ppA[tid + 256 * k];
    uint2 prB[4];
    if (np == 2) {
        int nB2 = 0xFFFF - (int)(keyB & 0xFFFFull);
        int trB = iB * 6272 + b * NGLOB + nB2;
        const uint2* ppB = g_tprob + (size_t)trB * (DIM / 4);
#pragma unroll
        for (int k = 0; k < 4; k++) prB[k] = ppB[tid + 256 * k];
    }

    float mx = -3.4e38f;
#pragma unroll
    for (int k = 0; k < 4; k++)
        mx = fmaxf(mx, fmaxf(fmaxf(v[k].x, v[k].y), fmaxf(v[k].z, v[k].w)));
    mx = blkMax(mx, sh);
    float se = 0.f;
#pragma unroll
    for (int k = 0; k < 4; k++)
        se += __expf(v[k].x - mx) + __expf(v[k].y - mx) + __expf(v[k].z - mx) + __expf(v[k].w - mx);
    se = blkSum(se, sh);
    float lse = mx + logf(se);

    float partA = 0.f, partB = 0.f;
#pragma unroll
    for (int k = 0; k < 4; k++) {
        float2 f0 = bf2f(prA[k].x);
        float2 f1 = bf2f(prA[k].y);
        partA += f0.x * v[k].x + f0.y * v[k].y + f1.x * v[k].z + f1.y * v[k].w;
    }
    if (np == 2) {
#pragma unroll
        for (int k = 0; k < 4; k++) {
            float2 f0 = bf2f(prB[k].x);
            float2 f1 = bf2f(prB[k].y);
            partB += f0.x * v[k].x + f0.y * v[k].y + f1.x * v[k].z + f1.y * v[k].w;
        }
    }
    float dotsum = blkSum(partA + partB, sh);

    if (tid == 0) {
        double contrib = ((double)np * (double)lse - (double)dotsum)
                       * (0.5 / ((double)S * 32.0 * 18.0));
        atomicAdd(&g_acc, contrib);
    }
}

// ---------------- K6: finalize ----------------
__global__ void k_fin(float* out) { out[0] = (float)g_acc; }

// ---------------- launch ----------------
extern "C" void kernel_launch(void* const* d_in, const int* in_sizes, int n_in,
                              void* d_out, int out_size) {
    (void)in_sizes; (void)n_in; (void)out_size;
    const float* s_cls  = (const float*)d_in[0];
    const float* s_reg  = (const float*)d_in[1];
    const float* s_fea  = (const float*)d_in[2];
    const float* t_cls  = (const float*)d_in[3];
    const float* t_reg  = (const float*)d_in[4];
    const float* t_fea  = (const float*)d_in[5];
    const float* center = (const float*)d_in[6];
    const float* cgrid  = (const float*)d_in[7];
    const int*   ep     = (const int*)d_in[8];

    static cudaStream_t s2 = nullptr;
    static cudaEvent_t e_fork = nullptr, e_join = nullptr;
    if (!s2) {
        cudaStreamCreateWithFlags(&s2, cudaStreamNonBlocking);
        cudaEventCreateWithFlags(&e_fork, cudaEventDisableTiming);
        cudaEventCreateWithFlags(&e_join, cudaEventDisableTiming);
    }

    // fork: prob + tcls on distinct stream
    cudaEventRecord(e_fork, cudaStreamPerThread);
    cudaStreamWaitEvent(s2, e_fork, 0);
    k_prob<<<TROWS, 256, 0, s2>>>(t_reg, cgrid, ep);
    k_tcls<<<64, 256, 0, s2>>>(t_cls, center, ep);
    cudaEventRecord(e_join, s2);

    // main chain: prep (norms + bf16 converts + init), bf16 sim
    k_prep<<<TN_BLKS + SC_BLKS + INIT_BLKS, 128>>>(s_fea, t_fea);
    k_sim<<<512, 256>>>();

    // join, then region+cls and finalize
    cudaStreamWaitEvent(cudaStreamPerThread, e_join, 0);
    k_regcls<<<SROWS + 576, 256>>>(s_reg, s_cls);
    k_fin<<<1, 1>>>((float*)d_out);
}